// round 2
// baseline (speedup 1.0000x reference)
#include <cuda_runtime.h>

// SatelliteImageGNN: 3-layer GCN on a 768x768 8-neighbor grid + 3x pixel shuffle.
//
// Transform: with dinv = 1/sqrt(deg) (position-determined on the grid),
//   layer(h) = (dinv .* BoxSum3x3(dinv .* h)) @ W + b
// edge_index is never read.
//
// This round: f32x2 packed math (FFMA2), channel-paired planar layout,
// 4 pixels/thread to amortize weight smem broadcasts, rolling row-sums.

#define H    768
#define NPIX (H * H)
#define OW   2304

typedef unsigned long long u64;

// Paired planar activations: pair j holds channels (2j, 2j+1).
__device__ float2 g_h1[16 * NPIX];
__device__ float2 g_h2[16 * NPIX];

__device__ __forceinline__ float dinv_at(int r, int c) {
    int rc = 1 + (r > 0) + (r < H - 1);
    int cc = 1 + (c > 0) + (c < H - 1);
    int n = rc * cc;                        // 4, 6, or 9
    return (n == 9) ? (1.0f / 3.0f)
         : ((n == 4) ? 0.5f : 0.40824829046386302f);
}

__device__ __forceinline__ u64 pack2(float lo, float hi) {
    u64 r; asm("mov.b64 %0,{%1,%2};" : "=l"(r) : "f"(lo), "f"(hi)); return r;
}
__device__ __forceinline__ void unpack2(u64 v, float& lo, float& hi) {
    asm("mov.b64 {%0,%1},%2;" : "=f"(lo), "=f"(hi) : "l"(v));
}
__device__ __forceinline__ u64 fma2(u64 a, u64 b, u64 c) {
    u64 d; asm("fma.rn.f32x2 %0,%1,%2,%3;" : "=l"(d) : "l"(a), "l"(b), "l"(c)); return d;
}
__device__ __forceinline__ u64 add2(u64 a, u64 b) {
    u64 d; asm("add.rn.f32x2 %0,%1,%2;" : "=l"(d) : "l"(a), "l"(b)); return d;
}
__device__ __forceinline__ u64 mul2(u64 a, u64 b) {
    u64 d; asm("mul.rn.f32x2 %0,%1,%2;" : "=l"(d) : "l"(a), "l"(b)); return d;
}

// ---------------------------------------------------------------------------
// Layer 1: x [N,3] interleaved -> g_h1 paired planar, ReLU.  16x16 tile.
// ---------------------------------------------------------------------------
__global__ __launch_bounds__(256) void layer1_kernel(
    const float* __restrict__ x,
    const float* __restrict__ W1,      // [3][32]
    const float* __restrict__ b1)
{
    __shared__ float U0[18 * 18], U1[18 * 18], U2[18 * 18];
    __shared__ u64 Ws[3][16];
    __shared__ u64 bs[16];

    const int tid = threadIdx.y * 16 + threadIdx.x;
    if (tid < 48) { int ch = tid / 16, j = tid % 16;
                    Ws[ch][j] = pack2(W1[ch * 32 + 2 * j], W1[ch * 32 + 2 * j + 1]); }
    if (tid < 16)  bs[tid] = pack2(b1[2 * tid], b1[2 * tid + 1]);

    const int tr = blockIdx.y * 16, tc = blockIdx.x * 16;

    for (int i = tid; i < 324; i += 256) {
        int lr = i / 18, lc = i - lr * 18;
        int gr = tr + lr - 1, gc = tc + lc - 1;
        float v0 = 0.f, v1 = 0.f, v2 = 0.f;
        if ((unsigned)gr < H && (unsigned)gc < H) {
            float d = dinv_at(gr, gc);
            const float* xp = x + (gr * H + gc) * 3;
            v0 = xp[0] * d; v1 = xp[1] * d; v2 = xp[2] * d;
        }
        U0[i] = v0; U1[i] = v1; U2[i] = v2;
    }
    __syncthreads();

    const int r = threadIdx.y, c = threadIdx.x;
    const int gr = tr + r, gc = tc + c;
    const float d = dinv_at(gr, gc);

    float s0 = 0.f, s1 = 0.f, s2 = 0.f;
#pragma unroll
    for (int dr = 0; dr < 3; dr++)
#pragma unroll
        for (int dc = 0; dc < 3; dc++) {
            int ix = (r + dr) * 18 + (c + dc);
            s0 += U0[ix]; s1 += U1[ix]; s2 += U2[ix];
        }
    s0 *= d; s1 *= d; s2 *= d;

    u64 A0 = pack2(s0, s0), A1 = pack2(s1, s1), A2 = pack2(s2, s2);
    const int pix = gr * H + gc;
#pragma unroll
    for (int j = 0; j < 16; j++) {
        u64 a = fma2(A0, Ws[0][j], bs[j]);
        a = fma2(A1, Ws[1][j], a);
        a = fma2(A2, Ws[2][j], a);
        float lo, hi; unpack2(a, lo, hi);
        g_h1[j * NPIX + pix] = make_float2(fmaxf(lo, 0.f), fmaxf(hi, 0.f));
    }
}

// ---------------------------------------------------------------------------
// Layers 2/3: paired planar in -> paired planar (ReLU) or shuffled output.
// Block 16x4 = 64 threads; each thread computes 4 vertically adjacent pixels.
// ---------------------------------------------------------------------------
template <int COP, bool SHUFFLE>       // COP = output pairs (16 or 5)
__global__ __launch_bounds__(64) void layer_mid_kernel(
    const float2* __restrict__ hin,    // paired planar [16][NPIX]
    const float* __restrict__ W,       // [32][COUT], COUT = SHUFFLE?9:32
    const float* __restrict__ b,
    float2* __restrict__ hout,
    float* __restrict__ osh)
{
    constexpr int COUT = SHUFFLE ? 9 : 32;
    __shared__ u64 U[16][324];         // 41472 B: all 16 input pairs, 18x18 halo
    __shared__ u64 Ws[32][COP];
    __shared__ u64 bs[COP];

    const int x = threadIdx.x;         // 0..15
    const int ty = threadIdx.y;        // 0..3
    const int tid = ty * 16 + x;

    for (int i = tid; i < 32 * COP; i += 64) {
        int k = i / COP, j = i - k * COP;
        float wlo = W[k * COUT + 2 * j];
        float whi = (2 * j + 1 < COUT) ? W[k * COUT + 2 * j + 1] : 0.f;
        Ws[k][j] = pack2(wlo, whi);
    }
    if (tid < COP) {
        float blo = b[2 * tid];
        float bhi = (2 * tid + 1 < COUT) ? b[2 * tid + 1] : 0.f;
        bs[tid] = pack2(blo, bhi);
    }

    const int tr = blockIdx.y * 16, tc = blockIdx.x * 16;

    // Fill halo tile for all 16 pairs, pre-scaled by source dinv.
    for (int i = tid; i < 16 * 324; i += 64) {
        int pr = i / 324, pos = i - pr * 324;
        int lr = pos / 18, lc = pos - lr * 18;
        int gr = tr + lr - 1, gc = tc + lc - 1;
        u64 v = 0;
        if ((unsigned)gr < H && (unsigned)gc < H) {
            float d = dinv_at(gr, gc);
            float2 t = hin[pr * NPIX + gr * H + gc];
            v = pack2(t.x * d, t.y * d);
        }
        U[pr][pos] = v;
    }
    __syncthreads();

    const int gc = tc + x;
    u64 dd[4];
#pragma unroll
    for (int p = 0; p < 4; p++) {
        float d = dinv_at(tr + 4 * ty + p, gc);
        dd[p] = pack2(d, d);
    }

    u64 acc[4][COP];
#pragma unroll
    for (int j = 0; j < COP; j++) {
        u64 bb = bs[j];
#pragma unroll
        for (int p = 0; p < 4; p++) acc[p][j] = bb;
    }

#pragma unroll
    for (int p8 = 0; p8 < 16; p8++) {
        // 7 rolling row-sums serve 4 output rows (4*ty .. 4*ty+3).
        u64 rs[7];
#pragma unroll
        for (int jj = 0; jj < 7; jj++) {
            int base = (4 * ty + jj) * 18 + x;
            rs[jj] = add2(add2(U[p8][base], U[p8][base + 1]), U[p8][base + 2]);
        }
        u64 A[4], B[4];
#pragma unroll
        for (int p = 0; p < 4; p++) {
            u64 s = add2(add2(rs[p], rs[p + 1]), rs[p + 2]);
            s = mul2(s, dd[p]);
            float sa, sb; unpack2(s, sa, sb);
            A[p] = pack2(sa, sa);               // stencil sum, channel 2*p8
            B[p] = pack2(sb, sb);               // channel 2*p8+1
        }
#pragma unroll
        for (int j = 0; j < COP; j++) {
            u64 w0 = Ws[2 * p8][j];             // broadcast LDS.64
            u64 w1 = Ws[2 * p8 + 1][j];
#pragma unroll
            for (int p = 0; p < 4; p++) {
                acc[p][j] = fma2(A[p], w0, acc[p][j]);
                acc[p][j] = fma2(B[p], w1, acc[p][j]);
            }
        }
    }

#pragma unroll
    for (int p = 0; p < 4; p++) {
        const int gr = tr + 4 * ty + p;
        if (SHUFFLE) {
            float v[2 * COP];
#pragma unroll
            for (int j = 0; j < COP; j++) unpack2(acc[p][j], v[2 * j], v[2 * j + 1]);
#pragma unroll
            for (int sy = 0; sy < 3; sy++) {
                int row = (gr * 3 + sy) * OW + gc * 3;
                osh[row + 0] = v[sy * 3 + 0];
                osh[row + 1] = v[sy * 3 + 1];
                osh[row + 2] = v[sy * 3 + 2];
            }
        } else {
            const int pix = gr * H + gc;
#pragma unroll
            for (int j = 0; j < COP; j++) {
                float lo, hi; unpack2(acc[p][j], lo, hi);
                hout[j * NPIX + pix] = make_float2(fmaxf(lo, 0.f), fmaxf(hi, 0.f));
            }
        }
    }
}

// ---------------------------------------------------------------------------

extern "C" void kernel_launch(void* const* d_in, const int* in_sizes, int n_in,
                              void* d_out, int out_size)
{
    const float* x  = (const float*)d_in[0];
    // d_in[1] = edge_index: unused (static 8-neighbor grid)
    const float* W1 = (const float*)d_in[2];
    const float* b1 = (const float*)d_in[3];
    const float* W2 = (const float*)d_in[4];
    const float* b2 = (const float*)d_in[5];
    const float* W3 = (const float*)d_in[6];
    const float* b3 = (const float*)d_in[7];
    float* out = (float*)d_out;

    float2* h1 = nullptr;
    float2* h2 = nullptr;
    cudaGetSymbolAddress((void**)&h1, g_h1);
    cudaGetSymbolAddress((void**)&h2, g_h2);

    dim3 grid(48, 48);
    dim3 blk1(16, 16);
    dim3 blk2(16, 4);

    layer1_kernel<<<grid, blk1>>>(x, W1, b1);
    layer_mid_kernel<16, false><<<grid, blk2>>>(h1, W2, b2, h2, nullptr);
    layer_mid_kernel<5, true><<<grid, blk2>>>(h2, W3, b3, nullptr, out);
}

// round 3
// speedup vs baseline: 1.8812x; 1.8812x over previous
#include <cuda_runtime.h>

// SatelliteImageGNN: 3-layer GCN on a 768x768 8-neighbor grid + 3x pixel shuffle.
//
// Transform: with dinv = 1/sqrt(deg) (position-determined on the grid),
//   layer(h) = (dinv .* BoxSum3x3(dinv .* h)) @ W + b
// edge_index is never read.
//
// R3: R1's 256-thread/1-pixel shape (occupancy) + f32x2 packed math,
// LDS.64 paired stencil reads, LDS.128 interleaved weight pairs.

#define H    768
#define NPIX (H * H)
#define OW   2304

typedef unsigned long long u64;

// Paired planar activations: pair j holds channels (2j, 2j+1).
__device__ float2 g_h1[16 * NPIX];
__device__ float2 g_h2[16 * NPIX];

__device__ __forceinline__ float dinv_at(int r, int c) {
    int rc = 1 + (r > 0) + (r < H - 1);
    int cc = 1 + (c > 0) + (c < H - 1);
    int n = rc * cc;                        // 4, 6, or 9
    return (n == 9) ? (1.0f / 3.0f)
         : ((n == 4) ? 0.5f : 0.40824829046386302f);
}

__device__ __forceinline__ u64 pack2(float lo, float hi) {
    u64 r; asm("mov.b64 %0,{%1,%2};" : "=l"(r) : "f"(lo), "f"(hi)); return r;
}
__device__ __forceinline__ void unpack2(u64 v, float& lo, float& hi) {
    asm("mov.b64 {%0,%1},%2;" : "=f"(lo), "=f"(hi) : "l"(v));
}
__device__ __forceinline__ u64 fma2(u64 a, u64 b, u64 c) {
    u64 d; asm("fma.rn.f32x2 %0,%1,%2,%3;" : "=l"(d) : "l"(a), "l"(b), "l"(c)); return d;
}
__device__ __forceinline__ u64 add2(u64 a, u64 b) {
    u64 d; asm("add.rn.f32x2 %0,%1,%2;" : "=l"(d) : "l"(a), "l"(b)); return d;
}
__device__ __forceinline__ u64 mul2(u64 a, u64 b) {
    u64 d; asm("mul.rn.f32x2 %0,%1,%2;" : "=l"(d) : "l"(a), "l"(b)); return d;
}

// ---------------------------------------------------------------------------
// Layer 1: x [N,3] interleaved -> g_h1 paired planar, ReLU.  16x16 tile.
// ---------------------------------------------------------------------------
__global__ __launch_bounds__(256) void layer1_kernel(
    const float* __restrict__ x,
    const float* __restrict__ W1,      // [3][32]
    const float* __restrict__ b1)
{
    __shared__ float U0[18 * 18], U1[18 * 18], U2[18 * 18];
    __shared__ u64 Ws[3][16];
    __shared__ u64 bs[16];

    const int tid = threadIdx.y * 16 + threadIdx.x;
    if (tid < 48) { int ch = tid / 16, j = tid % 16;
                    Ws[ch][j] = pack2(W1[ch * 32 + 2 * j], W1[ch * 32 + 2 * j + 1]); }
    if (tid < 16)  bs[tid] = pack2(b1[2 * tid], b1[2 * tid + 1]);

    const int tr = blockIdx.y * 16, tc = blockIdx.x * 16;

    for (int i = tid; i < 324; i += 256) {
        int lr = i / 18, lc = i - lr * 18;
        int gr = tr + lr - 1, gc = tc + lc - 1;
        float v0 = 0.f, v1 = 0.f, v2 = 0.f;
        if ((unsigned)gr < H && (unsigned)gc < H) {
            float d = dinv_at(gr, gc);
            const float* xp = x + (gr * H + gc) * 3;
            v0 = xp[0] * d; v1 = xp[1] * d; v2 = xp[2] * d;
        }
        U0[i] = v0; U1[i] = v1; U2[i] = v2;
    }
    __syncthreads();

    const int r = threadIdx.y, c = threadIdx.x;
    const int gr = tr + r, gc = tc + c;
    const float d = dinv_at(gr, gc);

    float s0 = 0.f, s1 = 0.f, s2 = 0.f;
#pragma unroll
    for (int dr = 0; dr < 3; dr++)
#pragma unroll
        for (int dc = 0; dc < 3; dc++) {
            int ix = (r + dr) * 18 + (c + dc);
            s0 += U0[ix]; s1 += U1[ix]; s2 += U2[ix];
        }
    s0 *= d; s1 *= d; s2 *= d;

    u64 A0 = pack2(s0, s0), A1 = pack2(s1, s1), A2 = pack2(s2, s2);
    const int pix = gr * H + gc;
#pragma unroll
    for (int j = 0; j < 16; j++) {
        u64 a = fma2(A0, Ws[0][j], bs[j]);
        a = fma2(A1, Ws[1][j], a);
        a = fma2(A2, Ws[2][j], a);
        float lo, hi; unpack2(a, lo, hi);
        g_h1[j * NPIX + pix] = make_float2(fmaxf(lo, 0.f), fmaxf(hi, 0.f));
    }
}

// ---------------------------------------------------------------------------
// Layers 2/3: paired planar in -> paired planar (ReLU) or shuffled output.
// 16x16 tile, 256 threads, ONE pixel per thread.
// ---------------------------------------------------------------------------
template <int COP, bool SHUFFLE>       // COP = output pairs (16 or 5)
__global__ __launch_bounds__(256) void layer_mid_kernel(
    const float2* __restrict__ hin,    // paired planar [16][NPIX]
    const float* __restrict__ W,       // [32][COUT], COUT = SHUFFLE?9:32
    const float* __restrict__ b,
    float2* __restrict__ hout,
    float* __restrict__ osh)
{
    constexpr int COUT = SHUFFLE ? 9 : 32;
    __shared__ u64 U[16][324];          // 41472 B
    __shared__ ulonglong2 Wp[16][COP];  // interleaved weight pairs
    __shared__ u64 bs[COP];

    const int tid = threadIdx.y * 16 + threadIdx.x;

    for (int i = tid; i < 16 * COP; i += 256) {
        int k8 = i / COP, j = i - k8 * COP;
        int r0 = (2 * k8) * COUT, r1 = (2 * k8 + 1) * COUT;
        float a0 = W[r0 + 2 * j];
        float a1 = (2 * j + 1 < COUT) ? W[r0 + 2 * j + 1] : 0.f;
        float c0 = W[r1 + 2 * j];
        float c1 = (2 * j + 1 < COUT) ? W[r1 + 2 * j + 1] : 0.f;
        ulonglong2 wp; wp.x = pack2(a0, a1); wp.y = pack2(c0, c1);
        Wp[k8][j] = wp;
    }
    if (tid < COP) {
        float blo = b[2 * tid];
        float bhi = (2 * tid + 1 < COUT) ? b[2 * tid + 1] : 0.f;
        bs[tid] = pack2(blo, bhi);
    }

    const int tr = blockIdx.y * 16, tc = blockIdx.x * 16;

    // Fill halo tile for all 16 pairs, pre-scaled by source dinv.
    for (int i = tid; i < 16 * 324; i += 256) {
        int pr = i / 324, pos = i - pr * 324;
        int lr = pos / 18, lc = pos - lr * 18;
        int gr = tr + lr - 1, gc = tc + lc - 1;
        u64 v = 0;
        if ((unsigned)gr < H && (unsigned)gc < H) {
            float d = dinv_at(gr, gc);
            float2 t = hin[pr * NPIX + gr * H + gc];
            v = pack2(t.x * d, t.y * d);
        }
        U[pr][pos] = v;
    }
    __syncthreads();

    const int r = threadIdx.y, c = threadIdx.x;
    const int gr = tr + r, gc = tc + c;
    const float dv = dinv_at(gr, gc);
    const u64 dd = pack2(dv, dv);

    u64 acc[COP];
#pragma unroll
    for (int j = 0; j < COP; j++) acc[j] = bs[j];

#pragma unroll
    for (int k8 = 0; k8 < 16; k8++) {
        const u64* Uk = U[k8] + r * 18 + c;
        u64 s = add2(add2(Uk[0],      Uk[1]),      Uk[2]);
        s = add2(s, add2(add2(Uk[18], Uk[19]),     Uk[20]));
        s = add2(s, add2(add2(Uk[36], Uk[37]),     Uk[38]));
        s = mul2(s, dd);
        float sa, sb; unpack2(s, sa, sb);
        u64 A = pack2(sa, sa);          // stencil sum, channel 2*k8 (both lanes)
        u64 B = pack2(sb, sb);          // channel 2*k8+1
#pragma unroll
        for (int j = 0; j < COP; j++) {
            ulonglong2 w = Wp[k8][j];   // LDS.128
            acc[j] = fma2(A, w.x, acc[j]);
            acc[j] = fma2(B, w.y, acc[j]);
        }
    }

    if (SHUFFLE) {
        float v[2 * COP];
#pragma unroll
        for (int j = 0; j < COP; j++) unpack2(acc[j], v[2 * j], v[2 * j + 1]);
#pragma unroll
        for (int sy = 0; sy < 3; sy++) {
            int row = (gr * 3 + sy) * OW + gc * 3;
            osh[row + 0] = v[sy * 3 + 0];
            osh[row + 1] = v[sy * 3 + 1];
            osh[row + 2] = v[sy * 3 + 2];
        }
    } else {
        const int pix = gr * H + gc;
#pragma unroll
        for (int j = 0; j < COP; j++) {
            float lo, hi; unpack2(acc[j], lo, hi);
            hout[j * NPIX + pix] = make_float2(fmaxf(lo, 0.f), fmaxf(hi, 0.f));
        }
    }
}

// ---------------------------------------------------------------------------

extern "C" void kernel_launch(void* const* d_in, const int* in_sizes, int n_in,
                              void* d_out, int out_size)
{
    const float* x  = (const float*)d_in[0];
    // d_in[1] = edge_index: unused (static 8-neighbor grid)
    const float* W1 = (const float*)d_in[2];
    const float* b1 = (const float*)d_in[3];
    const float* W2 = (const float*)d_in[4];
    const float* b2 = (const float*)d_in[5];
    const float* W3 = (const float*)d_in[6];
    const float* b3 = (const float*)d_in[7];
    float* out = (float*)d_out;

    float2* h1 = nullptr;
    float2* h2 = nullptr;
    cudaGetSymbolAddress((void**)&h1, g_h1);
    cudaGetSymbolAddress((void**)&h2, g_h2);

    dim3 grid(48, 48);
    dim3 blk(16, 16);

    layer1_kernel<<<grid, blk>>>(x, W1, b1);
    layer_mid_kernel<16, false><<<grid, blk>>>(h1, W2, b2, h2, nullptr);
    layer_mid_kernel<5, true><<<grid, blk>>>(h2, W3, b3, nullptr, out);
}

// round 4
// speedup vs baseline: 2.3653x; 1.2573x over previous
#include <cuda_runtime.h>

// SatelliteImageGNN: 3-layer GCN on a 768x768 8-neighbor grid + 3x pixel shuffle.
//
// Transform: with dinv = 1/sqrt(deg) (position-determined on the grid),
//   layer(h) = (dinv .* BoxSum3x3(dinv .* h)) @ W + b
// edge_index is never read.
//
// R4: FULL 3-LAYER FUSION. One kernel computes out tile 16x16 from x tile
// 22x22 entirely in shared memory (h1 20x20, h2 18x18 staged in smem).
// Global traffic drops ~380MB -> ~28MB. Interior tiles (dinv==1/3 everywhere)
// fold both normalizations into a single *1/9 and skip all bounds checks.

#define H    768
#define OW   2304

struct SM {
    float  X[3][22 * 22];        //  5808 B  input, (border: pre-scaled by dinv)
    float2 H1[16][20 * 20];      // 51200 B  layer1 out, channel pairs
    float2 H2[16][18 * 18];      // 41472 B  layer2 out, channel pairs
    float4 W1q[3][8];            // W1[ch][4j..]
    float4 W2q[32][8];           // W2[k][4j..]
    float2 W3p[16][9];           // (W3[2k][j], W3[2k+1][j])
    float4 b1q[8];
    float4 b2q[8];
    float  b3s[12];
};

__device__ __forceinline__ float dinv_at(int r, int c) {
    int rc = 1 + (r > 0) + (r < H - 1);
    int cc = 1 + (c > 0) + (c < H - 1);
    int n = rc * cc;                        // 4, 6, or 9
    return (n == 9) ? (1.0f / 3.0f)
         : ((n == 4) ? 0.5f : 0.40824829046386302f);
}

template <bool INTERIOR>
__device__ __forceinline__ void tile_compute(
    SM* sm, int tr, int tc,
    const float* __restrict__ x,
    const float* __restrict__ W1, const float* __restrict__ b1,
    const float* __restrict__ W2, const float* __restrict__ b2,
    const float* __restrict__ W3, const float* __restrict__ b3,
    float* __restrict__ out)
{
    const int tid = threadIdx.x;
    constexpr float NINTH = 1.0f / 9.0f;

    // ---- weights -> smem --------------------------------------------------
    if (tid < 24) {
        int ch = tid >> 3, j4 = tid & 7;
        sm->W1q[ch][j4] = *(const float4*)(W1 + ch * 32 + 4 * j4);
    }
    { int k = tid >> 3, j4 = tid & 7;
      sm->W2q[k][j4] = *(const float4*)(W2 + k * 32 + 4 * j4); }
    if (tid < 144) {
        int k8 = tid / 9, j = tid - k8 * 9;
        sm->W3p[k8][j] = make_float2(W3[(2 * k8) * 9 + j], W3[(2 * k8 + 1) * 9 + j]);
    }
    if (tid < 8)  sm->b1q[tid] = *(const float4*)(b1 + 4 * tid);
    else if (tid >= 16 && tid < 24) sm->b2q[tid - 16] = *(const float4*)(b2 + 4 * (tid - 16));
    if (tid >= 32 && tid < 41) sm->b3s[tid - 32] = b3[tid - 32];

    // ---- stage 0: x tile 22x22 -------------------------------------------
    for (int i = tid; i < 484; i += 256) {
        int xr = i / 22, xc = i - xr * 22;
        int gr = tr - 3 + xr, gc = tc - 3 + xc;
        float v0 = 0.f, v1 = 0.f, v2 = 0.f;
        if (INTERIOR) {
            const float* p = x + (gr * H + gc) * 3;
            v0 = p[0]; v1 = p[1]; v2 = p[2];
        } else if ((unsigned)gr < H && (unsigned)gc < H) {
            float d = dinv_at(gr, gc);
            const float* p = x + (gr * H + gc) * 3;
            v0 = p[0] * d; v1 = p[1] * d; v2 = p[2] * d;
        }
        sm->X[0][i] = v0; sm->X[1][i] = v1; sm->X[2][i] = v2;
    }
    __syncthreads();

    // ---- stage 1: h1 on 20x20 --------------------------------------------
    for (int p = tid; p < 400; p += 256) {
        int r = p / 20, c = p - r * 20;
        int base = r * 22 + c;
        float s0 = 0.f, s1 = 0.f, s2 = 0.f;
#pragma unroll
        for (int dr = 0; dr < 3; dr++) {
            int o = base + dr * 22;
            s0 += sm->X[0][o] + sm->X[0][o + 1] + sm->X[0][o + 2];
            s1 += sm->X[1][o] + sm->X[1][o + 1] + sm->X[1][o + 2];
            s2 += sm->X[2][o] + sm->X[2][o + 1] + sm->X[2][o + 2];
        }
        int gr = tr - 2 + r, gc = tc - 2 + c;
        float scale, post;
        bool valid = true;
        if (INTERIOR) { scale = NINTH; post = 1.f; }
        else {
            valid = (unsigned)gr < H && (unsigned)gc < H;
            float d = valid ? dinv_at(gr, gc) : 0.f;
            scale = d;            // dinv_dst for this layer's aggregation
            post  = d;            // dinv_src pre-scale for the next layer
        }
        s0 *= scale; s1 *= scale; s2 *= scale;

        float a[32];
#pragma unroll
        for (int j4 = 0; j4 < 8; j4++) {
            float4 bb = sm->b1q[j4];
            float4 w0 = sm->W1q[0][j4], w1 = sm->W1q[1][j4], w2 = sm->W1q[2][j4];
            a[4*j4+0] = fmaf(s2, w2.x, fmaf(s1, w1.x, fmaf(s0, w0.x, bb.x)));
            a[4*j4+1] = fmaf(s2, w2.y, fmaf(s1, w1.y, fmaf(s0, w0.y, bb.y)));
            a[4*j4+2] = fmaf(s2, w2.z, fmaf(s1, w1.z, fmaf(s0, w0.z, bb.z)));
            a[4*j4+3] = fmaf(s2, w2.w, fmaf(s1, w1.w, fmaf(s0, w0.w, bb.w)));
        }
#pragma unroll
        for (int j2 = 0; j2 < 16; j2++) {
            float lo = fmaxf(a[2*j2], 0.f), hi = fmaxf(a[2*j2+1], 0.f);
            if (!INTERIOR) { lo = valid ? lo * post : 0.f; hi = valid ? hi * post : 0.f; }
            sm->H1[j2][p] = make_float2(lo, hi);
        }
    }
    __syncthreads();

    // ---- stage 2: h2 on 18x18 --------------------------------------------
    for (int p = tid; p < 324; p += 256) {
        int r = p / 18, c = p - r * 18;
        int gr = tr - 1 + r, gc = tc - 1 + c;
        float scale, post;
        bool valid = true;
        if (INTERIOR) { scale = NINTH; post = 1.f; }
        else {
            valid = (unsigned)gr < H && (unsigned)gc < H;
            float d = valid ? dinv_at(gr, gc) : 0.f;
            scale = d; post = d;
        }

        float acc[32];
#pragma unroll
        for (int j4 = 0; j4 < 8; j4++) {
            float4 bb = sm->b2q[j4];
            acc[4*j4+0] = bb.x; acc[4*j4+1] = bb.y;
            acc[4*j4+2] = bb.z; acc[4*j4+3] = bb.w;
        }

        const int base = r * 20 + c;
#pragma unroll
        for (int k8 = 0; k8 < 16; k8++) {
            const float2* Up = sm->H1[k8] + base;
            float sx = 0.f, sy = 0.f;
#pragma unroll
            for (int dr = 0; dr < 3; dr++) {
                float2 u0 = Up[dr * 20], u1 = Up[dr * 20 + 1], u2 = Up[dr * 20 + 2];
                sx += u0.x + u1.x + u2.x;
                sy += u0.y + u1.y + u2.y;
            }
            sx *= scale; sy *= scale;
#pragma unroll
            for (int j4 = 0; j4 < 8; j4++) {
                float4 wa = sm->W2q[2 * k8][j4];
                float4 wb = sm->W2q[2 * k8 + 1][j4];
                acc[4*j4+0] = fmaf(sy, wb.x, fmaf(sx, wa.x, acc[4*j4+0]));
                acc[4*j4+1] = fmaf(sy, wb.y, fmaf(sx, wa.y, acc[4*j4+1]));
                acc[4*j4+2] = fmaf(sy, wb.z, fmaf(sx, wa.z, acc[4*j4+2]));
                acc[4*j4+3] = fmaf(sy, wb.w, fmaf(sx, wa.w, acc[4*j4+3]));
            }
        }
#pragma unroll
        for (int j2 = 0; j2 < 16; j2++) {
            float lo = fmaxf(acc[2*j2], 0.f), hi = fmaxf(acc[2*j2+1], 0.f);
            if (!INTERIOR) { lo = valid ? lo * post : 0.f; hi = valid ? hi * post : 0.f; }
            sm->H2[j2][p] = make_float2(lo, hi);
        }
    }
    __syncthreads();

    // ---- stage 3: out 16x16, pixel-shuffled ------------------------------
    {
        int r = tid >> 4, c = tid & 15;
        int gr = tr + r, gc = tc + c;
        float scale = INTERIOR ? NINTH : dinv_at(gr, gc);

        float acc[9];
#pragma unroll
        for (int j = 0; j < 9; j++) acc[j] = sm->b3s[j];

        const int base = r * 18 + c;
#pragma unroll
        for (int k8 = 0; k8 < 16; k8++) {
            const float2* Up = sm->H2[k8] + base;
            float sx = 0.f, sy = 0.f;
#pragma unroll
            for (int dr = 0; dr < 3; dr++) {
                float2 u0 = Up[dr * 18], u1 = Up[dr * 18 + 1], u2 = Up[dr * 18 + 2];
                sx += u0.x + u1.x + u2.x;
                sy += u0.y + u1.y + u2.y;
            }
            sx *= scale; sy *= scale;
#pragma unroll
            for (int j = 0; j < 9; j++) {
                float2 w = sm->W3p[k8][j];
                acc[j] = fmaf(sy, w.y, fmaf(sx, w.x, acc[j]));
            }
        }
#pragma unroll
        for (int sy3 = 0; sy3 < 3; sy3++) {
            int row = (gr * 3 + sy3) * OW + gc * 3;
            out[row + 0] = acc[sy3 * 3 + 0];
            out[row + 1] = acc[sy3 * 3 + 1];
            out[row + 2] = acc[sy3 * 3 + 2];
        }
    }
}

__global__ __launch_bounds__(256) void fused_interior_kernel(
    const float* __restrict__ x,
    const float* __restrict__ W1, const float* __restrict__ b1,
    const float* __restrict__ W2, const float* __restrict__ b2,
    const float* __restrict__ W3, const float* __restrict__ b3,
    float* __restrict__ out)
{
    extern __shared__ char smraw[];
    SM* sm = (SM*)smraw;
    int tr = (blockIdx.y + 1) * 16, tc = (blockIdx.x + 1) * 16;
    tile_compute<true>(sm, tr, tc, x, W1, b1, W2, b2, W3, b3, out);
}

__global__ __launch_bounds__(256) void fused_border_kernel(
    const float* __restrict__ x,
    const float* __restrict__ W1, const float* __restrict__ b1,
    const float* __restrict__ W2, const float* __restrict__ b2,
    const float* __restrict__ W3, const float* __restrict__ b3,
    float* __restrict__ out)
{
    int bx = blockIdx.x, by = blockIdx.y;
    if (bx >= 1 && bx <= 46 && by >= 1 && by <= 46) return;   // interior handled elsewhere
    extern __shared__ char smraw[];
    SM* sm = (SM*)smraw;
    tile_compute<false>(sm, by * 16, bx * 16, x, W1, b1, W2, b2, W3, b3, out);
}

// ---------------------------------------------------------------------------

extern "C" void kernel_launch(void* const* d_in, const int* in_sizes, int n_in,
                              void* d_out, int out_size)
{
    const float* x  = (const float*)d_in[0];
    // d_in[1] = edge_index: unused (static 8-neighbor grid)
    const float* W1 = (const float*)d_in[2];
    const float* b1 = (const float*)d_in[3];
    const float* W2 = (const float*)d_in[4];
    const float* b2 = (const float*)d_in[5];
    const float* W3 = (const float*)d_in[6];
    const float* b3 = (const float*)d_in[7];
    float* out = (float*)d_out;

    static bool attr_set = false;
    if (!attr_set) {
        cudaFuncSetAttribute(fused_interior_kernel,
                             cudaFuncAttributeMaxDynamicSharedMemorySize, (int)sizeof(SM));
        cudaFuncSetAttribute(fused_border_kernel,
                             cudaFuncAttributeMaxDynamicSharedMemorySize, (int)sizeof(SM));
        attr_set = true;
    }

    fused_interior_kernel<<<dim3(46, 46), 256, sizeof(SM)>>>(x, W1, b1, W2, b2, W3, b3, out);
    fused_border_kernel  <<<dim3(48, 48), 256, sizeof(SM)>>>(x, W1, b1, W2, b2, W3, b3, out);
}

// round 5
// speedup vs baseline: 3.0017x; 1.2691x over previous
#include <cuda_runtime.h>
#include <cuda_fp16.h>

// SatelliteImageGNN: 3-layer GCN on a 768x768 8-neighbor grid + 3x pixel shuffle.
//
// Transform: with dinv = 1/sqrt(deg) (position-determined on the grid),
//   layer(h) = (dinv .* BoxSum3x3(dinv .* h)) @ W + b
// edge_index is never read.
//
// R5: fully fused 3-layer tile pipeline (R4) +
//   - H1/H2 staged in smem as __half2 channel pairs  -> 58KB/block -> 3 blocks/SM
//   - box-sum stencils in HADD2 (2 channels/instr)
//   - single kernel: interior/border dispatch per block (no serialized tail)

#define H    768
#define OW   2304

struct SM {
    float   X[3][22 * 22];       //  5808 B  input (border: pre-scaled by dinv)
    __half2 H1[16][20 * 20];     // 25600 B  layer1 out, channel pairs
    __half2 H2[16][18 * 18];     // 20736 B  layer2 out, channel pairs
    float4  W1q[3][8];
    float4  W2q[32][8];
    float2  W3p[16][9];
    float4  b1q[8];
    float4  b2q[8];
    float   b3s[12];
};

__device__ __forceinline__ float dinv_at(int r, int c) {
    int rc = 1 + (r > 0) + (r < H - 1);
    int cc = 1 + (c > 0) + (c < H - 1);
    int n = rc * cc;                        // 4, 6, or 9
    return (n == 9) ? (1.0f / 3.0f)
         : ((n == 4) ? 0.5f : 0.40824829046386302f);
}

template <bool INTERIOR>
__device__ __forceinline__ void tile_compute(
    SM* sm, int tr, int tc,
    const float* __restrict__ x,
    const float* __restrict__ W1, const float* __restrict__ b1,
    const float* __restrict__ W2, const float* __restrict__ b2,
    const float* __restrict__ W3, const float* __restrict__ b3,
    float* __restrict__ out)
{
    const int tid = threadIdx.x;
    constexpr float NINTH = 1.0f / 9.0f;

    // ---- weights -> smem --------------------------------------------------
    if (tid < 24) {
        int ch = tid >> 3, j4 = tid & 7;
        sm->W1q[ch][j4] = *(const float4*)(W1 + ch * 32 + 4 * j4);
    }
    { int k = tid >> 3, j4 = tid & 7;
      sm->W2q[k][j4] = *(const float4*)(W2 + k * 32 + 4 * j4); }
    if (tid < 144) {
        int k8 = tid / 9, j = tid - k8 * 9;
        sm->W3p[k8][j] = make_float2(W3[(2 * k8) * 9 + j], W3[(2 * k8 + 1) * 9 + j]);
    }
    if (tid < 8)  sm->b1q[tid] = *(const float4*)(b1 + 4 * tid);
    else if (tid >= 16 && tid < 24) sm->b2q[tid - 16] = *(const float4*)(b2 + 4 * (tid - 16));
    if (tid >= 32 && tid < 41) sm->b3s[tid - 32] = b3[tid - 32];

    // ---- stage 0: x tile 22x22 -------------------------------------------
    for (int i = tid; i < 484; i += 256) {
        int xr = i / 22, xc = i - xr * 22;
        int gr = tr - 3 + xr, gc = tc - 3 + xc;
        float v0 = 0.f, v1 = 0.f, v2 = 0.f;
        if (INTERIOR) {
            const float* p = x + (gr * H + gc) * 3;
            v0 = p[0]; v1 = p[1]; v2 = p[2];
        } else if ((unsigned)gr < H && (unsigned)gc < H) {
            float d = dinv_at(gr, gc);
            const float* p = x + (gr * H + gc) * 3;
            v0 = p[0] * d; v1 = p[1] * d; v2 = p[2] * d;
        }
        sm->X[0][i] = v0; sm->X[1][i] = v1; sm->X[2][i] = v2;
    }
    __syncthreads();

    // ---- stage 1: h1 on 20x20 --------------------------------------------
    for (int p = tid; p < 400; p += 256) {
        int r = p / 20, c = p - r * 20;
        int base = r * 22 + c;
        float s0 = 0.f, s1 = 0.f, s2 = 0.f;
#pragma unroll
        for (int dr = 0; dr < 3; dr++) {
            int o = base + dr * 22;
            s0 += sm->X[0][o] + sm->X[0][o + 1] + sm->X[0][o + 2];
            s1 += sm->X[1][o] + sm->X[1][o + 1] + sm->X[1][o + 2];
            s2 += sm->X[2][o] + sm->X[2][o + 1] + sm->X[2][o + 2];
        }
        int gr = tr - 2 + r, gc = tc - 2 + c;
        float scale, post;
        bool valid = true;
        if (INTERIOR) { scale = NINTH; post = 1.f; }
        else {
            valid = (unsigned)gr < H && (unsigned)gc < H;
            float d = valid ? dinv_at(gr, gc) : 0.f;
            scale = d; post = d;
        }
        s0 *= scale; s1 *= scale; s2 *= scale;

        float a[32];
#pragma unroll
        for (int j4 = 0; j4 < 8; j4++) {
            float4 bb = sm->b1q[j4];
            float4 w0 = sm->W1q[0][j4], w1 = sm->W1q[1][j4], w2 = sm->W1q[2][j4];
            a[4*j4+0] = fmaf(s2, w2.x, fmaf(s1, w1.x, fmaf(s0, w0.x, bb.x)));
            a[4*j4+1] = fmaf(s2, w2.y, fmaf(s1, w1.y, fmaf(s0, w0.y, bb.y)));
            a[4*j4+2] = fmaf(s2, w2.z, fmaf(s1, w1.z, fmaf(s0, w0.z, bb.z)));
            a[4*j4+3] = fmaf(s2, w2.w, fmaf(s1, w1.w, fmaf(s0, w0.w, bb.w)));
        }
#pragma unroll
        for (int j2 = 0; j2 < 16; j2++) {
            float lo = fmaxf(a[2*j2], 0.f), hi = fmaxf(a[2*j2+1], 0.f);
            if (!INTERIOR) { lo = valid ? lo * post : 0.f; hi = valid ? hi * post : 0.f; }
            sm->H1[j2][p] = __floats2half2_rn(lo, hi);
        }
    }
    __syncthreads();

    // ---- stage 2: h2 on 18x18 --------------------------------------------
    for (int p = tid; p < 324; p += 256) {
        int r = p / 18, c = p - r * 18;
        int gr = tr - 1 + r, gc = tc - 1 + c;
        float scale, post;
        bool valid = true;
        if (INTERIOR) { scale = NINTH; post = 1.f; }
        else {
            valid = (unsigned)gr < H && (unsigned)gc < H;
            float d = valid ? dinv_at(gr, gc) : 0.f;
            scale = d; post = d;
        }

        float acc[32];
#pragma unroll
        for (int j4 = 0; j4 < 8; j4++) {
            float4 bb = sm->b2q[j4];
            acc[4*j4+0] = bb.x; acc[4*j4+1] = bb.y;
            acc[4*j4+2] = bb.z; acc[4*j4+3] = bb.w;
        }

        const int base = r * 20 + c;
#pragma unroll
        for (int k8 = 0; k8 < 16; k8++) {
            const __half2* Up = sm->H1[k8] + base;
            __half2 s = __hadd2(__hadd2(Up[0], Up[1]), Up[2]);
            s = __hadd2(s, __hadd2(__hadd2(Up[20], Up[21]), Up[22]));
            s = __hadd2(s, __hadd2(__hadd2(Up[40], Up[41]), Up[42]));
            float2 sf = __half22float2(s);
            float sx = sf.x * scale, sy = sf.y * scale;
#pragma unroll
            for (int j4 = 0; j4 < 8; j4++) {
                float4 wa = sm->W2q[2 * k8][j4];
                float4 wb = sm->W2q[2 * k8 + 1][j4];
                acc[4*j4+0] = fmaf(sy, wb.x, fmaf(sx, wa.x, acc[4*j4+0]));
                acc[4*j4+1] = fmaf(sy, wb.y, fmaf(sx, wa.y, acc[4*j4+1]));
                acc[4*j4+2] = fmaf(sy, wb.z, fmaf(sx, wa.z, acc[4*j4+2]));
                acc[4*j4+3] = fmaf(sy, wb.w, fmaf(sx, wa.w, acc[4*j4+3]));
            }
        }
#pragma unroll
        for (int j2 = 0; j2 < 16; j2++) {
            float lo = fmaxf(acc[2*j2], 0.f), hi = fmaxf(acc[2*j2+1], 0.f);
            if (!INTERIOR) { lo = valid ? lo * post : 0.f; hi = valid ? hi * post : 0.f; }
            sm->H2[j2][p] = __floats2half2_rn(lo, hi);
        }
    }
    __syncthreads();

    // ---- stage 3: out 16x16, pixel-shuffled ------------------------------
    {
        int r = tid >> 4, c = tid & 15;
        int gr = tr + r, gc = tc + c;
        float scale = INTERIOR ? NINTH : dinv_at(gr, gc);

        float acc[9];
#pragma unroll
        for (int j = 0; j < 9; j++) acc[j] = sm->b3s[j];

        const int base = r * 18 + c;
#pragma unroll
        for (int k8 = 0; k8 < 16; k8++) {
            const __half2* Up = sm->H2[k8] + base;
            __half2 s = __hadd2(__hadd2(Up[0], Up[1]), Up[2]);
            s = __hadd2(s, __hadd2(__hadd2(Up[18], Up[19]), Up[20]));
            s = __hadd2(s, __hadd2(__hadd2(Up[36], Up[37]), Up[38]));
            float2 sf = __half22float2(s);
            float sx = sf.x * scale, sy = sf.y * scale;
#pragma unroll
            for (int j = 0; j < 9; j++) {
                float2 w = sm->W3p[k8][j];
                acc[j] = fmaf(sy, w.y, fmaf(sx, w.x, acc[j]));
            }
        }
#pragma unroll
        for (int sy3 = 0; sy3 < 3; sy3++) {
            int row = (gr * 3 + sy3) * OW + gc * 3;
            out[row + 0] = acc[sy3 * 3 + 0];
            out[row + 1] = acc[sy3 * 3 + 1];
            out[row + 2] = acc[sy3 * 3 + 2];
        }
    }
}

__global__ __launch_bounds__(256, 3) void fused_kernel(
    const float* __restrict__ x,
    const float* __restrict__ W1, const float* __restrict__ b1,
    const float* __restrict__ W2, const float* __restrict__ b2,
    const float* __restrict__ W3, const float* __restrict__ b3,
    float* __restrict__ out)
{
    extern __shared__ char smraw[];
    SM* sm = (SM*)smraw;
    const int bx = blockIdx.x, by = blockIdx.y;
    if (bx >= 1 && bx <= 46 && by >= 1 && by <= 46)
        tile_compute<true>(sm, by * 16, bx * 16, x, W1, b1, W2, b2, W3, b3, out);
    else
        tile_compute<false>(sm, by * 16, bx * 16, x, W1, b1, W2, b2, W3, b3, out);
}

// ---------------------------------------------------------------------------

extern "C" void kernel_launch(void* const* d_in, const int* in_sizes, int n_in,
                              void* d_out, int out_size)
{
    const float* x  = (const float*)d_in[0];
    // d_in[1] = edge_index: unused (static 8-neighbor grid)
    const float* W1 = (const float*)d_in[2];
    const float* b1 = (const float*)d_in[3];
    const float* W2 = (const float*)d_in[4];
    const float* b2 = (const float*)d_in[5];
    const float* W3 = (const float*)d_in[6];
    const float* b3 = (const float*)d_in[7];
    float* out = (float*)d_out;

    static bool attr_set = false;
    if (!attr_set) {
        cudaFuncSetAttribute(fused_kernel,
                             cudaFuncAttributeMaxDynamicSharedMemorySize, (int)sizeof(SM));
        attr_set = true;
    }

    fused_kernel<<<dim3(48, 48), 256, sizeof(SM)>>>(x, W1, b1, W2, b2, W3, b3, out);
}

// round 7
// speedup vs baseline: 4.1844x; 1.3940x over previous
#include <cuda_runtime.h>
#include <cuda_fp16.h>

// SatelliteImageGNN: 3-layer GCN on a 768x768 8-neighbor grid + 3x pixel shuffle.
//
// Transform: with dinv = 1/sqrt(deg) (position-determined on the grid),
//   layer(h) = (dinv .* BoxSum3x3(dinv .* h)) @ W + b
// edge_index is never read.
//
// R7 = R6 (weights in __constant__, fp16-staged fused pipeline) with the
// graph-capture hazards fixed: cudaFuncSetAttribute guarded to run once, and
// the constant-bank update done via cudaGetSymbolAddress + cudaMemcpyAsync.

#define H    768
#define OW   2304

struct CPack {
    float W1[96];     // [3][32]
    float b1[32];
    float W2[1024];   // [32][32]
    float b2[32];
    float W3p[288];   // pair-interleaved: (W3[2k8][j], W3[2k8+1][j]) k8<16, j<9
    float b3[12];
};

__device__   CPack g_pack;   // staging (written by pack_kernel)
__constant__ CPack c_pack;   // read by fused kernel

__global__ __launch_bounds__(256) void pack_kernel(
    const float* __restrict__ W1, const float* __restrict__ b1,
    const float* __restrict__ W2, const float* __restrict__ b2,
    const float* __restrict__ W3, const float* __restrict__ b3)
{
    const int t = threadIdx.x;
    for (int i = t; i < 96; i += 256) g_pack.W1[i] = W1[i];
    for (int i = t; i < 1024; i += 256) g_pack.W2[i] = W2[i];
    if (t < 32) { g_pack.b1[t] = b1[t]; g_pack.b2[t] = b2[t]; }
    for (int i = t; i < 144; i += 256) {
        int k8 = i / 9, j = i - k8 * 9;
        g_pack.W3p[2 * i + 0] = W3[(2 * k8) * 9 + j];
        g_pack.W3p[2 * i + 1] = W3[(2 * k8 + 1) * 9 + j];
    }
    if (t < 12) g_pack.b3[t] = (t < 9) ? b3[t] : 0.f;
}

struct SM {
    float   X[3][22 * 22];       //  5808 B  input (border: pre-scaled by dinv)
    __half2 H1[16][20 * 20];     // 25600 B  layer1 out, channel pairs
    __half2 H2[16][18 * 18];     // 20736 B  layer2 out, channel pairs
};                               // 52144 B total

__device__ __forceinline__ float dinv_at(int r, int c) {
    int rc = 1 + (r > 0) + (r < H - 1);
    int cc = 1 + (c > 0) + (c < H - 1);
    int n = rc * cc;                        // 4, 6, or 9
    return (n == 9) ? (1.0f / 3.0f)
         : ((n == 4) ? 0.5f : 0.40824829046386302f);
}

template <bool INTERIOR>
__device__ __forceinline__ void tile_compute(
    SM* sm, int tr, int tc,
    const float* __restrict__ x,
    float* __restrict__ out)
{
    const int tid = threadIdx.x;
    constexpr float NINTH = 1.0f / 9.0f;

    // ---- stage 0: x tile 22x22 -------------------------------------------
    for (int i = tid; i < 484; i += 256) {
        int xr = i / 22, xc = i - xr * 22;
        int gr = tr - 3 + xr, gc = tc - 3 + xc;
        float v0 = 0.f, v1 = 0.f, v2 = 0.f;
        if (INTERIOR) {
            const float* p = x + (gr * H + gc) * 3;
            v0 = p[0]; v1 = p[1]; v2 = p[2];
        } else if ((unsigned)gr < H && (unsigned)gc < H) {
            float d = dinv_at(gr, gc);
            const float* p = x + (gr * H + gc) * 3;
            v0 = p[0] * d; v1 = p[1] * d; v2 = p[2] * d;
        }
        sm->X[0][i] = v0; sm->X[1][i] = v1; sm->X[2][i] = v2;
    }
    __syncthreads();

    // ---- stage 1: h1 on 20x20 --------------------------------------------
    for (int p = tid; p < 400; p += 256) {
        int r = p / 20, c = p - r * 20;
        int base = r * 22 + c;
        float s0 = 0.f, s1 = 0.f, s2 = 0.f;
#pragma unroll
        for (int dr = 0; dr < 3; dr++) {
            int o = base + dr * 22;
            s0 += sm->X[0][o] + sm->X[0][o + 1] + sm->X[0][o + 2];
            s1 += sm->X[1][o] + sm->X[1][o + 1] + sm->X[1][o + 2];
            s2 += sm->X[2][o] + sm->X[2][o + 1] + sm->X[2][o + 2];
        }
        int gr = tr - 2 + r, gc = tc - 2 + c;
        float scale, post;
        bool valid = true;
        if (INTERIOR) { scale = NINTH; post = 1.f; }
        else {
            valid = (unsigned)gr < H && (unsigned)gc < H;
            float d = valid ? dinv_at(gr, gc) : 0.f;
            scale = d; post = d;
        }
        s0 *= scale; s1 *= scale; s2 *= scale;

        float a[32];
#pragma unroll
        for (int j4 = 0; j4 < 8; j4++) {
            float4 bb = *(const float4*)(c_pack.b1 + 4 * j4);
            float4 w0 = *(const float4*)(c_pack.W1 +       4 * j4);
            float4 w1 = *(const float4*)(c_pack.W1 + 32  + 4 * j4);
            float4 w2 = *(const float4*)(c_pack.W1 + 64  + 4 * j4);
            a[4*j4+0] = fmaf(s2, w2.x, fmaf(s1, w1.x, fmaf(s0, w0.x, bb.x)));
            a[4*j4+1] = fmaf(s2, w2.y, fmaf(s1, w1.y, fmaf(s0, w0.y, bb.y)));
            a[4*j4+2] = fmaf(s2, w2.z, fmaf(s1, w1.z, fmaf(s0, w0.z, bb.z)));
            a[4*j4+3] = fmaf(s2, w2.w, fmaf(s1, w1.w, fmaf(s0, w0.w, bb.w)));
        }
#pragma unroll
        for (int j2 = 0; j2 < 16; j2++) {
            float lo = fmaxf(a[2*j2], 0.f), hi = fmaxf(a[2*j2+1], 0.f);
            if (!INTERIOR) { lo = valid ? lo * post : 0.f; hi = valid ? hi * post : 0.f; }
            sm->H1[j2][p] = __floats2half2_rn(lo, hi);
        }
    }
    __syncthreads();

    // ---- stage 2: h2 on 18x18 --------------------------------------------
    for (int p = tid; p < 324; p += 256) {
        int r = p / 18, c = p - r * 18;
        int gr = tr - 1 + r, gc = tc - 1 + c;
        float scale, post;
        bool valid = true;
        if (INTERIOR) { scale = NINTH; post = 1.f; }
        else {
            valid = (unsigned)gr < H && (unsigned)gc < H;
            float d = valid ? dinv_at(gr, gc) : 0.f;
            scale = d; post = d;
        }

        float acc[32];
#pragma unroll
        for (int j4 = 0; j4 < 8; j4++) {
            float4 bb = *(const float4*)(c_pack.b2 + 4 * j4);
            acc[4*j4+0] = bb.x; acc[4*j4+1] = bb.y;
            acc[4*j4+2] = bb.z; acc[4*j4+3] = bb.w;
        }

        const int base = r * 20 + c;
#pragma unroll
        for (int k8 = 0; k8 < 16; k8++) {
            const __half2* Up = sm->H1[k8] + base;
            __half2 s = __hadd2(__hadd2(Up[0], Up[1]), Up[2]);
            s = __hadd2(s, __hadd2(__hadd2(Up[20], Up[21]), Up[22]));
            s = __hadd2(s, __hadd2(__hadd2(Up[40], Up[41]), Up[42]));
            float2 sf = __half22float2(s);
            float sx = sf.x * scale, sy = sf.y * scale;
#pragma unroll
            for (int j4 = 0; j4 < 8; j4++) {
                float4 wa = *(const float4*)(c_pack.W2 + (2 * k8) * 32 + 4 * j4);
                float4 wb = *(const float4*)(c_pack.W2 + (2 * k8 + 1) * 32 + 4 * j4);
                acc[4*j4+0] = fmaf(sy, wb.x, fmaf(sx, wa.x, acc[4*j4+0]));
                acc[4*j4+1] = fmaf(sy, wb.y, fmaf(sx, wa.y, acc[4*j4+1]));
                acc[4*j4+2] = fmaf(sy, wb.z, fmaf(sx, wa.z, acc[4*j4+2]));
                acc[4*j4+3] = fmaf(sy, wb.w, fmaf(sx, wa.w, acc[4*j4+3]));
            }
        }
#pragma unroll
        for (int j2 = 0; j2 < 16; j2++) {
            float lo = fmaxf(acc[2*j2], 0.f), hi = fmaxf(acc[2*j2+1], 0.f);
            if (!INTERIOR) { lo = valid ? lo * post : 0.f; hi = valid ? hi * post : 0.f; }
            sm->H2[j2][p] = __floats2half2_rn(lo, hi);
        }
    }
    __syncthreads();

    // ---- stage 3: out 16x16, pixel-shuffled ------------------------------
    {
        int r = tid >> 4, c = tid & 15;
        int gr = tr + r, gc = tc + c;
        float scale = INTERIOR ? NINTH : dinv_at(gr, gc);

        float acc[9];
#pragma unroll
        for (int j = 0; j < 9; j++) acc[j] = c_pack.b3[j];

        const int base = r * 18 + c;
#pragma unroll
        for (int k8 = 0; k8 < 16; k8++) {
            const __half2* Up = sm->H2[k8] + base;
            __half2 s = __hadd2(__hadd2(Up[0], Up[1]), Up[2]);
            s = __hadd2(s, __hadd2(__hadd2(Up[18], Up[19]), Up[20]));
            s = __hadd2(s, __hadd2(__hadd2(Up[36], Up[37]), Up[38]));
            float2 sf = __half22float2(s);
            float sx = sf.x * scale, sy = sf.y * scale;
#pragma unroll
            for (int j = 0; j < 9; j++) {
                float2 w = *(const float2*)(c_pack.W3p + 2 * (k8 * 9 + j));
                acc[j] = fmaf(sy, w.y, fmaf(sx, w.x, acc[j]));
            }
        }
#pragma unroll
        for (int sy3 = 0; sy3 < 3; sy3++) {
            int row = (gr * 3 + sy3) * OW + gc * 3;
            out[row + 0] = acc[sy3 * 3 + 0];
            out[row + 1] = acc[sy3 * 3 + 1];
            out[row + 2] = acc[sy3 * 3 + 2];
        }
    }
}

__global__ __launch_bounds__(256, 3) void fused_kernel(
    const float* __restrict__ x,
    float* __restrict__ out)
{
    extern __shared__ char smraw[];
    SM* sm = (SM*)smraw;
    const int bx = blockIdx.x, by = blockIdx.y;
    if (bx >= 1 && bx <= 46 && by >= 1 && by <= 46)
        tile_compute<true>(sm, by * 16, bx * 16, x, out);
    else
        tile_compute<false>(sm, by * 16, bx * 16, x, out);
}

// ---------------------------------------------------------------------------

extern "C" void kernel_launch(void* const* d_in, const int* in_sizes, int n_in,
                              void* d_out, int out_size)
{
    const float* x  = (const float*)d_in[0];
    // d_in[1] = edge_index: unused (static 8-neighbor grid)
    const float* W1 = (const float*)d_in[2];
    const float* b1 = (const float*)d_in[3];
    const float* W2 = (const float*)d_in[4];
    const float* b2 = (const float*)d_in[5];
    const float* W3 = (const float*)d_in[6];
    const float* b3 = (const float*)d_in[7];
    float* out = (float*)d_out;

    // One-time, outside-of-capture safe: attribute setting must NOT happen
    // during the harness's graph-capture call (R6's container failure).
    static bool attr_set = false;
    if (!attr_set) {
        cudaFuncSetAttribute(fused_kernel,
                             cudaFuncAttributeMaxDynamicSharedMemorySize, (int)sizeof(SM));
        attr_set = true;
    }

    pack_kernel<<<1, 256>>>(W1, b1, W2, b2, W3, b3);

    // Update the constant bank with a plain capturable DtoD memcpy node.
    void* gp = nullptr;
    void* cp = nullptr;
    cudaGetSymbolAddress(&gp, g_pack);
    cudaGetSymbolAddress(&cp, c_pack);
    cudaMemcpyAsync(cp, gp, sizeof(CPack), cudaMemcpyDeviceToDevice, 0);

    fused_kernel<<<dim3(48, 48), 256, sizeof(SM)>>>(x, out);
}